// round 7
// baseline (speedup 1.0000x reference)
#include <cuda_runtime.h>
#include <cuda_bf16.h>
#include <cstdint>

#define Vn 55
#define Cn 64
#define Dn 64
#define Tn 128
#define Nn 64
#define NTn 8192
#define VD 3520
#define TOTAL (NTn * VD)       // 28,835,840

#define RS 72                  // padded row stride in bf16 elements (36 words)

__device__ float g_buf[TOTAL];            // g in [n][t][d][v]
__device__ float d_mU[4096];              // mask [u*64+k] = tanh(fm[u*64+k])+1
__device__ float d_A1T[4096];             // BN1 scale, [d*64+u]
__device__ float d_B1T[4096];             // BN1 shift (bias folded), [d*64+u]
__device__ float d_A2[Dn];
__device__ float d_B2[Dn];
__device__ __nv_bfloat16 d_WhB[64 * RS];  // W^T hi, [d*RS + c]
__device__ __nv_bfloat16 d_WlB[64 * RS];  // W^T lo residual

__device__ __forceinline__ void mma16(float* c, const unsigned* a, const unsigned* b) {
    asm volatile(
        "mma.sync.aligned.m16n8k16.row.col.f32.bf16.bf16.f32 "
        "{%0,%1,%2,%3}, {%4,%5,%6,%7}, {%8,%9}, {%0,%1,%2,%3};"
        : "+f"(c[0]), "+f"(c[1]), "+f"(c[2]), "+f"(c[3])
        : "r"(a[0]), "r"(a[1]), "r"(a[2]), "r"(a[3]), "r"(b[0]), "r"(b[1]));
}

// ---- prep: one-time tables -------------------------------------------------
__global__ __launch_bounds__(256) void prep_kernel(
    const float* __restrict__ W, const float* __restrict__ b,
    const float* __restrict__ fm,
    const float* __restrict__ g1, const float* __restrict__ be1,
    const float* __restrict__ m1, const float* __restrict__ v1,
    const float* __restrict__ g2, const float* __restrict__ be2,
    const float* __restrict__ m2, const float* __restrict__ v2)
{
    int i = blockIdx.x * 256 + threadIdx.x;   // 0..4095
    if (i < 4096) {
        // mask [u][k]
        int u = i >> 6;
        float mval = 0.0f;
        if (u < Vn) mval = tanhf(fm[i]) + 1.0f;
        d_mU[i] = mval;

        // W^T split hi/lo, padded rows: i = c*64+d
        int c = i >> 6, d = i & 63;
        float w = W[i];
        __nv_bfloat16 h = __float2bfloat16(w);
        float lo = w - __bfloat162float(h);
        d_WhB[d * RS + c] = h;
        d_WlB[d * RS + c] = __float2bfloat16(lo);
    }
    if (i < VD) {
        int u = i >> 6, d = i & 63;
        float a = g1[i] * rsqrtf(v1[i] + 1e-5f);
        d_A1T[d * 64 + u] = a;
        d_B1T[d * 64 + u] = be1[i] + a * (b[d] - m1[i]);
    }
    if (i < Dn) {
        float a = g2[i] * rsqrtf(v2[i] + 1e-5f);
        d_A2[i] = a;
        d_B2[i] = be2[i] - a * m2[i];
    }
}

// ---- kernelA: 2 t per block; shift+mask -> bf16x3 mma GEMM -> BN1+shift ----
// Dyn smem 55296 B: AH[0,18432) AL[18432,36864) BH[36864,46080) BL[46080,55296)
// Stage (2*3520 floats = 28160 B) overlays AH/AL after GEMM.
#define SMEMA_BYTES 55296

__global__ __launch_bounds__(256) void kernelA(const float* __restrict__ x)
{
    extern __shared__ __align__(16) char smraw[];
    __nv_bfloat16* AH = (__nv_bfloat16*)smraw;      // [row*RS + k], row = tl*64+u
    __nv_bfloat16* AL = AH + 128 * RS;
    __nv_bfloat16* BH = AL + 128 * RS;              // [d*RS + k]
    __nv_bfloat16* BL = BH + 64 * RS;

    const int tid = threadIdx.x;
    const int n  = blockIdx.x >> 6;
    const int t0 = (blockIdx.x & 63) << 1;

    // Copy W tiles (pre-split/padded): 9216 B each = 576 float4
    {
        float4* bh4 = (float4*)BH;
        float4* bl4 = (float4*)BL;
        const float4* gh4 = (const float4*)d_WhB;
        const float4* gl4 = (const float4*)d_WlB;
        for (int i = tid; i < 576; i += 256) { bh4[i] = gh4[i]; bl4[i] = gl4[i]; }
    }

    // Build A (paired k, bf16x2 words): A[row][k] = x[n,k,t0+tl,(u+k)%55]*m[u][k]
    unsigned* AHw = (unsigned*)AH;   // 36 words per row
    unsigned* ALw = (unsigned*)AL;
    const float* xb = x + ((size_t)n * Cn * Tn + t0) * Vn;
    for (int iw = tid; iw < 4096; iw += 256) {
        int row = iw >> 5;            // 0..127
        int kw  = iw & 31;            // word index
        int k   = kw << 1;
        int tl  = row >> 6;
        int u   = row & 63;
        float v0 = 0.0f, v1 = 0.0f;
        if (u < Vn) {
            int s0 = u + k;
            if (s0 >= Vn) s0 -= Vn;
            if (s0 >= Vn) s0 -= Vn;
            int s1 = s0 + 1;
            if (s1 >= Vn) s1 -= Vn;
            const float* xt = xb + tl * Vn;
            float2 m2v = *(const float2*)&d_mU[u * 64 + k];
            v0 = xt[(size_t)k * (Tn * Vn) + s0] * m2v.x;
            v1 = xt[(size_t)(k + 1) * (Tn * Vn) + s1] * m2v.y;
        }
        __nv_bfloat162 h2 = __float22bfloat162_rn(make_float2(v0, v1));
        float l0 = v0 - __bfloat162float(h2.x);
        float l1 = v1 - __bfloat162float(h2.y);
        __nv_bfloat162 l2 = __float22bfloat162_rn(make_float2(l0, l1));
        AHw[row * 36 + kw] = *(unsigned*)&h2;
        ALw[row * 36 + kw] = *(unsigned*)&l2;
    }
    __syncthreads();

    // GEMM: y[row][d] = sum_k A[row][k] * WT[d][k].  M=128 N=64 K=64.
    // warp w: rows w*16..w*16+15, all 64 d (8 n-tiles).
    const int w = tid >> 5;
    const int lane = tid & 31;
    const int lr = lane >> 2;
    const int lc = lane & 3;
    const int rb = w * 16;

    const unsigned* BHw = (const unsigned*)BH;
    const unsigned* BLw = (const unsigned*)BL;

    float acc[8][4];
#pragma unroll
    for (int i = 0; i < 8; i++)
#pragma unroll
        for (int j = 0; j < 4; j++) acc[i][j] = 0.0f;

#pragma unroll
    for (int s = 0; s < 4; s++) {               // k0 = s*16
        const int abase = (rb + lr) * 36 + s * 8 + lc;
        unsigned ah[4], al[4];
        ah[0] = AHw[abase];
        ah[1] = AHw[abase + 8 * 36];
        ah[2] = AHw[abase + 4];
        ah[3] = AHw[abase + 8 * 36 + 4];
        al[0] = ALw[abase];
        al[1] = ALw[abase + 8 * 36];
        al[2] = ALw[abase + 4];
        al[3] = ALw[abase + 8 * 36 + 4];
#pragma unroll
        for (int ntile = 0; ntile < 8; ntile++) {
            const int bbase = (ntile * 8 + lr) * 36 + s * 8 + lc;
            unsigned bh[2], bl[2];
            bh[0] = BHw[bbase];
            bh[1] = BHw[bbase + 4];
            bl[0] = BLw[bbase];
            bl[1] = BLw[bbase + 4];
            mma16(acc[ntile], ah, bh);
            mma16(acc[ntile], ah, bl);
            mma16(acc[ntile], al, bh);
        }
    }
    __syncthreads();   // GEMM smem reads done; reuse A region as staging

    // Epilogue: BN1 + ReLU + inverse shift into stage[tl][d*55 + (u+d)%55]
    float* stage = (float*)smraw;   // 2*3520 floats, overlays AH/AL
#pragma unroll
    for (int i = 0; i < 4; i++) {
        int r = rb + lr + ((i & 2) ? 8 : 0);
        int tl = r >> 6;
        int u = r & 63;
        if (u < Vn) {
            float* st = stage + tl * VD;
#pragma unroll
            for (int ntile = 0; ntile < 8; ntile++) {
                int d = ntile * 8 + lc * 2 + (i & 1);
                int j = d * 64 + u;
                float y = fmaxf(d_A1T[j] * acc[ntile][i] + d_B1T[j], 0.0f);
                int vv = u + d;
                if (vv >= Vn) vv -= Vn;
                if (vv >= Vn) vv -= Vn;
                st[d * Vn + vv] = y;
            }
        }
    }
    __syncthreads();

    // Coalesced store g[n][t0..t0+1][d][v]
    {
        float4* gout = (float4*)&g_buf[(size_t)(((n << 7) | t0)) * VD];
        const float4* ss = (const float4*)stage;
        for (int i = tid; i < 1760; i += 256) gout[i] = ss[i];
    }
}

// ---- kernelB: temporal shift + BN2 + residual + ReLU (float4) --------------
__global__ __launch_bounds__(256) void kernelB(const float* __restrict__ x,
                                               float* __restrict__ out)
{
    int gid = blockIdx.x * 256 + threadIdx.x;   // < 7,208,960
    int i0 = gid * 4;
    int nc = i0 / 7040;                // (n*64+c); all 4 elems in same chunk
    int rem = i0 - nc * 7040;
    int c = nc & 63;
    int n = nc >> 6;
    float a2 = d_A2[c], b2 = d_B2[c];
    int off = (c % 3) - 1;
    const float* gb = &g_buf[(size_t)(n * Tn) * VD + c * Vn];

    float4 xv = *(const float4*)(x + i0);
    float xr[4] = {xv.x, xv.y, xv.z, xv.w};
    float r[4];
#pragma unroll
    for (int e = 0; e < 4; e++) {
        int re = rem + e;
        int t = re / 55;
        int v = re - t * 55;
        int tt = t + off;
        float gv = 0.0f;
        if ((unsigned)tt < (unsigned)Tn) gv = gb[(size_t)tt * VD + v];
        r[e] = fmaxf(a2 * gv + b2 + xr[e], 0.0f);
    }
    float4 ov = {r[0], r[1], r[2], r[3]};
    *(float4*)(out + i0) = ov;
}

extern "C" void kernel_launch(void* const* d_in, const int* in_sizes, int n_in,
                              void* d_out, int out_size)
{
    const float* x   = (const float*)d_in[0];
    const float* W   = (const float*)d_in[1];
    const float* b   = (const float*)d_in[2];
    const float* fm  = (const float*)d_in[3];
    const float* g1  = (const float*)d_in[4];
    const float* be1 = (const float*)d_in[5];
    const float* m1  = (const float*)d_in[6];
    const float* v1  = (const float*)d_in[7];
    const float* g2  = (const float*)d_in[8];
    const float* be2 = (const float*)d_in[9];
    const float* m2  = (const float*)d_in[10];
    const float* v2  = (const float*)d_in[11];
    float* out = (float*)d_out;

    static int smem_set = 0;
    if (!smem_set) {
        cudaFuncSetAttribute(kernelA, cudaFuncAttributeMaxDynamicSharedMemorySize,
                             SMEMA_BYTES);
        smem_set = 1;
    }

    prep_kernel<<<16, 256>>>(W, b, fm, g1, be1, m1, v1, g2, be2, m2, v2);
    kernelA<<<NTn / 2, 256, SMEMA_BYTES>>>(x);
    kernelB<<<TOTAL / 1024, 256>>>(x, out);
}

// round 8
// speedup vs baseline: 1.5091x; 1.5091x over previous
#include <cuda_runtime.h>
#include <cuda_bf16.h>
#include <cstdint>

#define Vn 55
#define Cn 64
#define Dn 64
#define Tn 128
#define Nn 64
#define NTn 8192
#define VD 3520
#define TOTAL (NTn * VD)       // 28,835,840

#define RS 72                  // padded row stride in bf16 elements (36 words)

__device__ float g_buf[TOTAL];            // g in [n][t][d][v]
__device__ float d_mU[4096];              // mask [u*64+k] = tanh(fm[u*64+k])+1
__device__ float d_A1T[4096];             // BN1 scale, [d*64+u]
__device__ float d_B1T[4096];             // BN1 shift (bias folded), [d*64+u]
__device__ float d_A2[Dn];
__device__ float d_B2[Dn];
__device__ __nv_bfloat16 d_WhB[64 * RS];  // W^T hi, [d*RS + c]
__device__ __nv_bfloat16 d_WlB[64 * RS];  // W^T lo residual

__device__ __forceinline__ void mma16(float* c, const unsigned* a, const unsigned* b) {
    asm volatile(
        "mma.sync.aligned.m16n8k16.row.col.f32.bf16.bf16.f32 "
        "{%0,%1,%2,%3}, {%4,%5,%6,%7}, {%8,%9}, {%0,%1,%2,%3};"
        : "+f"(c[0]), "+f"(c[1]), "+f"(c[2]), "+f"(c[3])
        : "r"(a[0]), "r"(a[1]), "r"(a[2]), "r"(a[3]), "r"(b[0]), "r"(b[1]));
}

// ---- prep: one-time tables -------------------------------------------------
__global__ __launch_bounds__(256) void prep_kernel(
    const float* __restrict__ W, const float* __restrict__ b,
    const float* __restrict__ fm,
    const float* __restrict__ g1, const float* __restrict__ be1,
    const float* __restrict__ m1, const float* __restrict__ v1,
    const float* __restrict__ g2, const float* __restrict__ be2,
    const float* __restrict__ m2, const float* __restrict__ v2)
{
    int i = blockIdx.x * 256 + threadIdx.x;   // 0..4095
    if (i < 4096) {
        // mask [u][k]
        int u = i >> 6;
        float mval = 0.0f;
        if (u < Vn) mval = tanhf(fm[i]) + 1.0f;
        d_mU[i] = mval;

        // W^T split hi/lo, padded rows: i = c*64+d
        int c = i >> 6, d = i & 63;
        float w = W[i];
        __nv_bfloat16 h = __float2bfloat16(w);
        float lo = w - __bfloat162float(h);
        d_WhB[d * RS + c] = h;
        d_WlB[d * RS + c] = __float2bfloat16(lo);
    }
    if (i < VD) {
        int u = i >> 6, d = i & 63;
        float a = g1[i] * rsqrtf(v1[i] + 1e-5f);
        d_A1T[d * 64 + u] = a;
        d_B1T[d * 64 + u] = be1[i] + a * (b[d] - m1[i]);
    }
    if (i < Dn) {
        float a = g2[i] * rsqrtf(v2[i] + 1e-5f);
        d_A2[i] = a;
        d_B2[i] = be2[i] - a * m2[i];
    }
}

// ---- kernelA: shift+mask -> bf16x3 mma GEMM -> BN1+ReLU+inverse shift ------
// Static smem 36864 B: AH[0,9216) AL[9216,18432) BH[18432,27648) BL[27648,36864)
// Stage (3520 floats = 14080 B) overlays AH/AL after GEMM.
__global__ __launch_bounds__(256) void kernelA(const float* __restrict__ x)
{
    __shared__ __align__(16) char smraw[36864];
    __nv_bfloat16* AH = (__nv_bfloat16*)smraw;              // [u*RS + k]
    __nv_bfloat16* AL = AH + 64 * RS;
    __nv_bfloat16* BH = AL + 64 * RS;                       // [d*RS + k]
    __nv_bfloat16* BL = BH + 64 * RS;

    const int tid = threadIdx.x;
    const int nt = blockIdx.x;
    const int n = nt >> 7;
    const int t = nt & 127;

    // Copy W tiles (pre-split/padded): 9216 B each = 576 float4
    {
        float4* bh4 = (float4*)BH;
        float4* bl4 = (float4*)BL;
        const float4* gh4 = (const float4*)d_WhB;
        const float4* gl4 = (const float4*)d_WlB;
        for (int i = tid; i < 576; i += 256) { bh4[i] = gh4[i]; bl4[i] = gl4[i]; }
    }

    // Build A (paired k, bf16x2 words): A[u][k] = x[n,k,t,(u+k)%55] * m[u][k]
    unsigned* AHw = (unsigned*)AH;   // 36 words per row
    unsigned* ALw = (unsigned*)AL;
    const float* xnt = x + ((size_t)n * Cn * Tn + t) * Vn;
    for (int iw = tid; iw < 2048; iw += 256) {
        int u  = iw >> 5;             // 0..63
        int kw = iw & 31;             // word index
        int k  = kw << 1;
        float v0 = 0.0f, v1 = 0.0f;
        if (u < Vn) {
            int s0 = u + k;
            if (s0 >= Vn) s0 -= Vn;
            if (s0 >= Vn) s0 -= Vn;
            int s1 = s0 + 1;
            if (s1 >= Vn) s1 -= Vn;
            float2 m2v = *(const float2*)&d_mU[u * 64 + k];
            v0 = xnt[(size_t)k * (Tn * Vn) + s0] * m2v.x;
            v1 = xnt[(size_t)(k + 1) * (Tn * Vn) + s1] * m2v.y;
        }
        __nv_bfloat162 h2 = __float22bfloat162_rn(make_float2(v0, v1));
        float l0 = v0 - __bfloat162float(h2.x);
        float l1 = v1 - __bfloat162float(h2.y);
        __nv_bfloat162 l2 = __float22bfloat162_rn(make_float2(l0, l1));
        AHw[u * 36 + kw] = *(unsigned*)&h2;
        ALw[u * 36 + kw] = *(unsigned*)&l2;
    }
    __syncthreads();

    // GEMM: y[u][d] = sum_k A[u][k] * WT[d][k].  M=64 N=64 K=64.
    // warp w: rows ub..ub+15 (w&3), cols nb..nb+31 (w>>2), 4 n8-tiles.
    const int w = tid >> 5;
    const int lane = tid & 31;
    const int lr = lane >> 2;    // group (0..7)
    const int lc = lane & 3;     // thread-in-group (0..3)
    const int ub = (w & 3) * 16;
    const int nb = (w >> 2) * 32;

    const unsigned* BHw = (const unsigned*)BH;
    const unsigned* BLw = (const unsigned*)BL;

    float acc[4][4];
#pragma unroll
    for (int i = 0; i < 4; i++)
#pragma unroll
        for (int j = 0; j < 4; j++) acc[i][j] = 0.0f;

#pragma unroll
    for (int s = 0; s < 4; s++) {               // k0 = s*16
        const int abase = (ub + lr) * 36 + s * 8 + lc;
        unsigned ah[4], al[4];
        ah[0] = AHw[abase];
        ah[1] = AHw[abase + 8 * 36];
        ah[2] = AHw[abase + 4];
        ah[3] = AHw[abase + 8 * 36 + 4];
        al[0] = ALw[abase];
        al[1] = ALw[abase + 8 * 36];
        al[2] = ALw[abase + 4];
        al[3] = ALw[abase + 8 * 36 + 4];
#pragma unroll
        for (int ntile = 0; ntile < 4; ntile++) {
            const int bbase = (nb + ntile * 8 + lr) * 36 + s * 8 + lc;
            unsigned bh[2], bl[2];
            bh[0] = BHw[bbase];
            bh[1] = BHw[bbase + 4];
            bl[0] = BLw[bbase];
            bl[1] = BLw[bbase + 4];
            mma16(acc[ntile], ah, bh);
            mma16(acc[ntile], ah, bl);
            mma16(acc[ntile], al, bh);
        }
    }
    __syncthreads();   // GEMM smem reads done; reuse A region as staging

    // Epilogue: BN1 + ReLU + inverse shift into stage[d*55 + (u+d)%55]
    float* stage = (float*)smraw;
#pragma unroll
    for (int i = 0; i < 4; i++) {
        int u = ub + lr + ((i & 2) ? 8 : 0);
        if (u < Vn) {
#pragma unroll
            for (int ntile = 0; ntile < 4; ntile++) {
                int d = nb + ntile * 8 + lc * 2 + (i & 1);
                int j = d * 64 + u;
                float y = fmaxf(d_A1T[j] * acc[ntile][i] + d_B1T[j], 0.0f);
                int vv = u + d;
                if (vv >= Vn) vv -= Vn;
                if (vv >= Vn) vv -= Vn;
                stage[d * Vn + vv] = y;
            }
        }
    }
    __syncthreads();

    // Coalesced store g[n][t][d][v]
    {
        float4* gout = (float4*)&g_buf[(size_t)nt * VD];
        const float4* ss = (const float4*)stage;
        for (int i = tid; i < 880; i += 256) gout[i] = ss[i];
    }
}

// ---- kernelB: temporal shift + BN2 + residual + ReLU (float4) --------------
__global__ __launch_bounds__(256) void kernelB(const float* __restrict__ x,
                                               float* __restrict__ out)
{
    int gid = blockIdx.x * 256 + threadIdx.x;   // < 7,208,960
    int i0 = gid * 4;
    int nc = i0 / 7040;                // (n*64+c); all 4 elems in same chunk
    int rem = i0 - nc * 7040;
    int c = nc & 63;
    int n = nc >> 6;
    float a2 = d_A2[c], b2 = d_B2[c];
    int off = (c % 3) - 1;
    const float* gb = &g_buf[(size_t)(n * Tn) * VD + c * Vn];

    float4 xv = *(const float4*)(x + i0);
    float xr[4] = {xv.x, xv.y, xv.z, xv.w};
    float r[4];
#pragma unroll
    for (int e = 0; e < 4; e++) {
        int re = rem + e;
        int t = re / 55;
        int v = re - t * 55;
        int tt = t + off;
        float gv = 0.0f;
        if ((unsigned)tt < (unsigned)Tn) gv = gb[(size_t)tt * VD + v];
        r[e] = fmaxf(a2 * gv + b2 + xr[e], 0.0f);
    }
    float4 ov = {r[0], r[1], r[2], r[3]};
    *(float4*)(out + i0) = ov;
}

extern "C" void kernel_launch(void* const* d_in, const int* in_sizes, int n_in,
                              void* d_out, int out_size)
{
    const float* x   = (const float*)d_in[0];
    const float* W   = (const float*)d_in[1];
    const float* b   = (const float*)d_in[2];
    const float* fm  = (const float*)d_in[3];
    const float* g1  = (const float*)d_in[4];
    const float* be1 = (const float*)d_in[5];
    const float* m1  = (const float*)d_in[6];
    const float* v1  = (const float*)d_in[7];
    const float* g2  = (const float*)d_in[8];
    const float* be2 = (const float*)d_in[9];
    const float* m2  = (const float*)d_in[10];
    const float* v2  = (const float*)d_in[11];
    float* out = (float*)d_out;

    prep_kernel<<<16, 256>>>(W, b, fm, g1, be1, m1, v1, g2, be2, m2, v2);
    kernelA<<<NTn, 256>>>(x);
    kernelB<<<TOTAL / 1024, 256>>>(x, out);
}

// round 9
// speedup vs baseline: 1.6519x; 1.0946x over previous
#include <cuda_runtime.h>
#include <cuda_bf16.h>
#include <cstdint>

#define Vn 55
#define Cn 64
#define Dn 64
#define Tn 128
#define Nn 64
#define NTn 8192
#define VD 3520
#define TOTAL (NTn * VD)       // 28,835,840

#define RS 72                  // padded row stride in bf16 elements (36 words)

__device__ float g_buf[TOTAL];            // g in [n][t][d][v]
__device__ float2 d_mP[2048];             // mask pairs: [kp*64+u] = (m[2kp][u], m[2kp+1][u])
__device__ float d_A1T[4096];             // BN1 scale, [d*64+u]
__device__ float d_B1T[4096];             // BN1 shift (bias folded), [d*64+u]
__device__ float d_A2[Dn];
__device__ float d_B2[Dn];
__device__ __nv_bfloat16 d_WhB[64 * RS];  // W^T hi, [d*RS + c]
__device__ __nv_bfloat16 d_WlB[64 * RS];  // W^T lo residual

__device__ __forceinline__ void mma16(float* c, const unsigned* a, const unsigned* b) {
    asm volatile(
        "mma.sync.aligned.m16n8k16.row.col.f32.bf16.bf16.f32 "
        "{%0,%1,%2,%3}, {%4,%5,%6,%7}, {%8,%9}, {%0,%1,%2,%3};"
        : "+f"(c[0]), "+f"(c[1]), "+f"(c[2]), "+f"(c[3])
        : "r"(a[0]), "r"(a[1]), "r"(a[2]), "r"(a[3]), "r"(b[0]), "r"(b[1]));
}

// ---- prep: one-time tables -------------------------------------------------
__global__ __launch_bounds__(256) void prep_kernel(
    const float* __restrict__ W, const float* __restrict__ b,
    const float* __restrict__ fm,
    const float* __restrict__ g1, const float* __restrict__ be1,
    const float* __restrict__ m1, const float* __restrict__ v1,
    const float* __restrict__ g2, const float* __restrict__ be2,
    const float* __restrict__ m2, const float* __restrict__ v2)
{
    int i = blockIdx.x * 256 + threadIdx.x;   // 0..4095
    if (i < 2048) {
        // mask pair table: kp = i>>6, u = i&63
        int kp = i >> 6, u = i & 63;
        float m0 = 0.0f, m1v = 0.0f;
        if (u < Vn) {
            m0 = tanhf(fm[u * Cn + 2 * kp]) + 1.0f;
            m1v = tanhf(fm[u * Cn + 2 * kp + 1]) + 1.0f;
        }
        d_mP[i] = make_float2(m0, m1v);
    }
    if (i < 4096) {
        // W^T split hi/lo, padded rows: i = c*64+d
        int c = i >> 6, d = i & 63;
        float w = W[i];
        __nv_bfloat16 h = __float2bfloat16(w);
        float lo = w - __bfloat162float(h);
        d_WhB[d * RS + c] = h;
        d_WlB[d * RS + c] = __float2bfloat16(lo);
    }
    if (i < VD) {
        int u = i >> 6, d = i & 63;
        float a = g1[i] * rsqrtf(v1[i] + 1e-5f);
        d_A1T[d * 64 + u] = a;
        d_B1T[d * 64 + u] = be1[i] + a * (b[d] - m1[i]);
    }
    if (i < Dn) {
        float a = g2[i] * rsqrtf(v2[i] + 1e-5f);
        d_A2[i] = a;
        d_B2[i] = be2[i] - a * m2[i];
    }
}

// ---- kernelA: shift+mask -> bf16x3 mma GEMM -> BN1+ReLU+inverse shift ------
// Static smem 36864 B: AH[0,9216) AL[9216,18432) BH[18432,27648) BL[27648,36864)
// A rows use XOR swizzle on the k-word index: kw' = kw ^ ((u>>3)&3).
// Stage (3520 floats = 14080 B) overlays AH/AL after GEMM.
__global__ __launch_bounds__(256) void kernelA(const float* __restrict__ x)
{
    __shared__ __align__(16) char smraw[36864];
    __nv_bfloat16* AH = (__nv_bfloat16*)smraw;              // [u*RS + k], swizzled
    __nv_bfloat16* AL = AH + 64 * RS;
    __nv_bfloat16* BH = AL + 64 * RS;                       // [d*RS + k]
    __nv_bfloat16* BL = BH + 64 * RS;

    const int tid = threadIdx.x;
    const int nt = blockIdx.x;
    const int n = nt >> 7;
    const int t = nt & 127;

    // Copy W tiles (pre-split/padded): 9216 B each = 576 float4
    {
        float4* bh4 = (float4*)BH;
        float4* bl4 = (float4*)BL;
        const float4* gh4 = (const float4*)d_WhB;
        const float4* gl4 = (const float4*)d_WlB;
        for (int i = tid; i < 576; i += 256) { bh4[i] = gh4[i]; bl4[i] = gl4[i]; }
    }

    // Build A: lanes span u (coalesced x reads), k-pair fixed per warp.
    // A[u][k] = x[n,k,t,(u+k)%55] * m[k][u]; zero pad rows u=55..63.
    unsigned* AHw = (unsigned*)AH;   // 36 words per row
    unsigned* ALw = (unsigned*)AL;
    const float* xnt = x + ((size_t)n * Cn * Tn + t) * Vn;
    for (int iw = tid; iw < 2048; iw += 256) {
        int u  = (iw & 31) + ((iw >> 10) << 5);   // lane + 32*half
        int kp = (iw >> 5) & 31;
        int k  = kp << 1;
        float v0 = 0.0f, v1 = 0.0f;
        if (u < Vn) {
            int s0 = u + k;
            if (s0 >= Vn) s0 -= Vn;
            if (s0 >= Vn) s0 -= Vn;
            int s1 = s0 + 1;
            if (s1 >= Vn) s1 -= Vn;
            float2 m2v = d_mP[kp * 64 + u];
            v0 = xnt[(size_t)k * (Tn * Vn) + s0] * m2v.x;
            v1 = xnt[(size_t)(k + 1) * (Tn * Vn) + s1] * m2v.y;
        }
        __nv_bfloat162 h2 = __float22bfloat162_rn(make_float2(v0, v1));
        float l0 = v0 - __bfloat162float(h2.x);
        float l1 = v1 - __bfloat162float(h2.y);
        __nv_bfloat162 l2 = __float22bfloat162_rn(make_float2(l0, l1));
        int kws = kp ^ ((u >> 3) & 3);            // XOR swizzle
        AHw[u * 36 + kws] = *(unsigned*)&h2;
        ALw[u * 36 + kws] = *(unsigned*)&l2;
    }
    __syncthreads();

    // GEMM: y[u][d] = sum_k A[u][k] * WT[d][k].  M=64 N=64 K=64.
    // warp w: rows ub..ub+15 (w&3), cols nb..nb+31 (w>>2), 4 n8-tiles.
    const int w = tid >> 5;
    const int lane = tid & 31;
    const int lr = lane >> 2;    // group (0..7)
    const int lc = lane & 3;     // thread-in-group (0..3)
    const int ub = (w & 3) * 16;
    const int nb = (w >> 2) * 32;

    const unsigned* BHw = (const unsigned*)BH;
    const unsigned* BLw = (const unsigned*)BL;

    // Swizzle constants for the two A row groups (rows ub+lr and ub+lr+8)
    const int row0 = ub + lr;
    const int row1 = row0 + 8;
    const int lcs0 = lc ^ ((row0 >> 3) & 3);
    const int lcs1 = lc ^ ((row1 >> 3) & 3);

    float acc[4][4];
#pragma unroll
    for (int i = 0; i < 4; i++)
#pragma unroll
        for (int j = 0; j < 4; j++) acc[i][j] = 0.0f;

#pragma unroll
    for (int s = 0; s < 4; s++) {               // k0 = s*16
        const int a0 = row0 * 36 + s * 8 + lcs0;
        const int a1 = row1 * 36 + s * 8 + lcs1;
        unsigned ah[4], al[4];
        ah[0] = AHw[a0];
        ah[1] = AHw[a1];
        ah[2] = AHw[a0 + 4];
        ah[3] = AHw[a1 + 4];
        al[0] = ALw[a0];
        al[1] = ALw[a1];
        al[2] = ALw[a0 + 4];
        al[3] = ALw[a1 + 4];
#pragma unroll
        for (int ntile = 0; ntile < 4; ntile++) {
            const int bbase = (nb + ntile * 8 + lr) * 36 + s * 8 + lc;
            unsigned bh[2], bl[2];
            bh[0] = BHw[bbase];
            bh[1] = BHw[bbase + 4];
            bl[0] = BLw[bbase];
            bl[1] = BLw[bbase + 4];
            mma16(acc[ntile], ah, bh);
            mma16(acc[ntile], ah, bl);
            mma16(acc[ntile], al, bh);
        }
    }
    __syncthreads();   // GEMM smem reads done; reuse A region as staging

    // Epilogue: BN1 + ReLU + inverse shift into stage[d*55 + (u+d)%55]
    float* stage = (float*)smraw;
#pragma unroll
    for (int i = 0; i < 4; i++) {
        int u = ub + lr + ((i & 2) ? 8 : 0);
        if (u < Vn) {
#pragma unroll
            for (int ntile = 0; ntile < 4; ntile++) {
                int d = nb + ntile * 8 + lc * 2 + (i & 1);
                int j = d * 64 + u;
                float y = fmaxf(d_A1T[j] * acc[ntile][i] + d_B1T[j], 0.0f);
                int vv = u + d;
                if (vv >= Vn) vv -= Vn;
                if (vv >= Vn) vv -= Vn;
                stage[d * Vn + vv] = y;
            }
        }
    }
    __syncthreads();

    // Coalesced store g[n][t][d][v]
    {
        float4* gout = (float4*)&g_buf[(size_t)nt * VD];
        const float4* ss = (const float4*)stage;
        for (int i = tid; i < 880; i += 256) gout[i] = ss[i];
    }
}

// ---- kernelB: temporal shift + BN2 + residual + ReLU (float4) --------------
__global__ __launch_bounds__(256) void kernelB(const float* __restrict__ x,
                                               float* __restrict__ out)
{
    int gid = blockIdx.x * 256 + threadIdx.x;   // < 7,208,960
    int i0 = gid * 4;
    int nc = i0 / 7040;                // (n*64+c); all 4 elems in same chunk
    int rem = i0 - nc * 7040;
    int c = nc & 63;
    int n = nc >> 6;
    float a2 = d_A2[c], b2 = d_B2[c];
    int off = (c % 3) - 1;
    const float* gb = &g_buf[(size_t)(n * Tn) * VD + c * Vn];

    float4 xv = *(const float4*)(x + i0);
    float xr[4] = {xv.x, xv.y, xv.z, xv.w};
    float r[4];
#pragma unroll
    for (int e = 0; e < 4; e++) {
        int re = rem + e;
        int t = re / 55;
        int v = re - t * 55;
        int tt = t + off;
        float gv = 0.0f;
        if ((unsigned)tt < (unsigned)Tn) gv = gb[(size_t)tt * VD + v];
        r[e] = fmaxf(a2 * gv + b2 + xr[e], 0.0f);
    }
    float4 ov = {r[0], r[1], r[2], r[3]};
    *(float4*)(out + i0) = ov;
}

extern "C" void kernel_launch(void* const* d_in, const int* in_sizes, int n_in,
                              void* d_out, int out_size)
{
    const float* x   = (const float*)d_in[0];
    const float* W   = (const float*)d_in[1];
    const float* b   = (const float*)d_in[2];
    const float* fm  = (const float*)d_in[3];
    const float* g1  = (const float*)d_in[4];
    const float* be1 = (const float*)d_in[5];
    const float* m1  = (const float*)d_in[6];
    const float* v1  = (const float*)d_in[7];
    const float* g2  = (const float*)d_in[8];
    const float* be2 = (const float*)d_in[9];
    const float* m2  = (const float*)d_in[10];
    const float* v2  = (const float*)d_in[11];
    float* out = (float*)d_out;

    prep_kernel<<<16, 256>>>(W, b, fm, g1, be1, m1, v1, g2, be2, m2, v2);
    kernelA<<<NTn, 256>>>(x);
    kernelB<<<TOTAL / 1024, 256>>>(x, out);
}